// round 7
// baseline (speedup 1.0000x reference)
#include <cuda_runtime.h>

#define B_DIM 128
#define C_DIM 2048
#define HW 196
#define NC 8
#define NM 4
#define NOUT 24                    // 8 A (m_c pre-bias) + 8 Z + 8 Y
#define PART_N (B_DIM * HW)        // 25088
#define SLABS 8
#define CSLAB (C_DIM / SLABS)      // 256

// ---- scratch (__device__ globals; no allocation allowed) ----
// slab-partial per-pixel outputs: [slab][out24][g]  (19.3 MB, L2-resident)
__device__ float g_part[SLABS * NOUT * PART_N];

// ---------------- packed f32x2 helpers ----------------
__device__ __forceinline__ unsigned long long fma2(
    unsigned long long a, unsigned long long b, unsigned long long c) {
    unsigned long long d;
    asm("fma.rn.f32x2 %0, %1, %2, %3;" : "=l"(d) : "l"(a), "l"(b), "l"(c));
    return d;
}
__device__ __forceinline__ unsigned long long dup2(float v) {
    unsigned long long d;
    asm("mov.b64 %0, {%1, %2};" : "=l"(d) : "f"(v), "f"(v));
    return d;
}
__device__ __forceinline__ void unpack2(unsigned long long v, float& lo, float& hi) {
    asm("mov.b64 {%0, %1}, %2;" : "=f"(lo), "=f"(hi) : "l"(v));
}

// ============================================================================
// K1: single streaming pass over x. grid (98, 8), 256 threads, 3 blocks/SM.
// Thread owns pixel-batch index g; 24 accumulators (12 packed f32x2):
//   A[k] = w_eff[k]·x   (m_c pre-bias)
//   Z[k] = w_lo[k]·x    (for sum_p Z = w_lo·gap_x)
//   Y[k] = w_hi[k]·x    (for sum_p m·Y = w_hi·gap_u)
// over the 256 channels of its slab. 16-channel LDG batches keep ~300 issued
// instructions between dependent uses -> DRAM latency fully covered.
// Inline weight fold into smem (24 KB).
// ============================================================================
__global__ void __launch_bounds__(256, 3) k1_main(
    const float* __restrict__ x,
    const float* __restrict__ w_down,
    const float* __restrict__ w_cls) {
    __shared__ float wsh[CSLAB * NOUT];   // 24 KB

    const int slab = blockIdx.y;
    const int t = threadIdx.x;

    // ---- inline weight prep: thread t owns local channel t ----
    {
        const int cg = slab * CSLAB + t;
        float* w = &wsh[t * NOUT];
#pragma unroll
        for (int k = 0; k < NC; ++k) {
            float s0 = w_down[(k * NM + 0) * C_DIM + cg];
            float s1 = w_down[(k * NM + 1) * C_DIM + cg];
            float s2 = w_down[(k * NM + 2) * C_DIM + cg];
            float s3 = w_down[(k * NM + 3) * C_DIM + cg];
            w[k]      = 0.25f * ((s0 + s1) + (s2 + s3));
            w[8 + k]  = w_cls[k * 2 * C_DIM + cg];
            w[16 + k] = w_cls[k * 2 * C_DIM + C_DIM + cg];
        }
    }
    __syncthreads();

    const int g = blockIdx.x * 256 + t;
    const int b = g / HW;
    const int p = g - b * HW;

    unsigned long long acc[12];
#pragma unroll
    for (int j = 0; j < 12; ++j) acc[j] = dup2(0.f);

    const float* xp = x + (size_t)b * C_DIM * HW + (size_t)(slab * CSLAB) * HW + p;

#pragma unroll 1
    for (int c0 = 0; c0 < CSLAB; c0 += 16) {
        // front-batch 16 independent global loads (MLP = 16)
        float xv[16];
#pragma unroll
        for (int u = 0; u < 16; ++u) xv[u] = __ldg(&xp[(c0 + u) * HW]);
#pragma unroll
        for (int u = 0; u < 16; ++u) {
            unsigned long long xx = dup2(xv[u]);
            const ulonglong2* w = (const ulonglong2*)&wsh[(c0 + u) * NOUT];
            ulonglong2 w0 = w[0];
            ulonglong2 w1 = w[1];
            ulonglong2 w2 = w[2];
            acc[0]  = fma2(xx, w0.x, acc[0]);
            acc[1]  = fma2(xx, w0.y, acc[1]);
            acc[2]  = fma2(xx, w1.x, acc[2]);
            acc[3]  = fma2(xx, w1.y, acc[3]);
            acc[4]  = fma2(xx, w2.x, acc[4]);
            acc[5]  = fma2(xx, w2.y, acc[5]);
            ulonglong2 w3 = w[3];
            ulonglong2 w4 = w[4];
            ulonglong2 w5 = w[5];
            acc[6]  = fma2(xx, w3.x, acc[6]);
            acc[7]  = fma2(xx, w3.y, acc[7]);
            acc[8]  = fma2(xx, w4.x, acc[8]);
            acc[9]  = fma2(xx, w4.y, acc[9]);
            acc[10] = fma2(xx, w5.x, acc[10]);
            acc[11] = fma2(xx, w5.y, acc[11]);
        }
    }

    // write 24 slab-partials, coalesced per output row
    float* base = &g_part[(size_t)slab * NOUT * PART_N + g];
#pragma unroll
    for (int j = 0; j < 12; ++j) {
        float lo, hi;
        unpack2(acc[j], lo, hi);
        base[(2 * j) * PART_N]     = lo;
        base[(2 * j + 1) * PART_N] = hi;
    }
}

// ============================================================================
// K2: per-batch epilogue. 128 blocks x 224 threads (196 active pixels).
//   m_c[k,p] = sum_s A_part + beff[k]                 -> out_mc, smem
//   v[k]     = mean_p m_c                             -> out_v
//   m[p]     = (1/8) sum_k v[k]*m_c[k,p]              -> out_m
//   output[k]= (1/HW) sum_p (Z[k,p] + m[p]*Y[k,p]) + b_cls[k]
// All gmem loads batched 16-deep (partials live in L2).
// ============================================================================
__global__ void __launch_bounds__(224) k2_epi(
    const float* __restrict__ b_down,
    const float* __restrict__ b_cls,
    float* __restrict__ out_v,
    float* __restrict__ out_output,
    float* __restrict__ out_m,
    float* __restrict__ out_mc) {
    __shared__ float red[NC * 200];
    __shared__ float vsh[NC];
    __shared__ float besh[NC];
    __shared__ float wpart[7][NC];

    const int b = blockIdx.x;
    const int t = threadIdx.x;
    const int g0 = b * HW;

    if (t < NC)
        besh[t] = 0.25f * (b_down[4 * t] + b_down[4 * t + 1] +
                           b_down[4 * t + 2] + b_down[4 * t + 3]);
    __syncthreads();

    // ---- m_c: two k's per round -> 16 loads in flight ----
    if (t < HW) {
#pragma unroll
        for (int kk = 0; kk < NC; kk += 2) {
            float a0[SLABS], a1[SLABS];
#pragma unroll
            for (int s = 0; s < SLABS; ++s)
                a0[s] = g_part[((size_t)s * NOUT + kk) * PART_N + g0 + t];
#pragma unroll
            for (int s = 0; s < SLABS; ++s)
                a1[s] = g_part[((size_t)s * NOUT + kk + 1) * PART_N + g0 + t];
            float s0 = ((a0[0] + a0[1]) + (a0[2] + a0[3])) +
                       ((a0[4] + a0[5]) + (a0[6] + a0[7]));
            float s1 = ((a1[0] + a1[1]) + (a1[2] + a1[3])) +
                       ((a1[4] + a1[5]) + (a1[6] + a1[7]));
            float mc0 = s0 + besh[kk];
            float mc1 = s1 + besh[kk + 1];
            red[kk * 200 + t] = mc0;
            red[(kk + 1) * 200 + t] = mc1;
            out_mc[((size_t)b * NC + kk) * HW + t] = mc0;
            out_mc[((size_t)b * NC + kk + 1) * HW + t] = mc1;
        }
    }
    __syncthreads();

    if (t < NC) {
        float s = 0.f;
        for (int p = 0; p < HW; ++p) s += red[t * 200 + p];
        float vv = s * (1.0f / (float)HW);
        vsh[t] = vv;
        out_v[b * NC + t] = vv;
    }
    __syncthreads();

    float m = 0.f;
    if (t < HW) {
#pragma unroll
        for (int k = 0; k < NC; ++k) m = fmaf(vsh[k], red[k * 200 + t], m);
        m *= (1.0f / (float)NC);
        out_m[b * HW + t] = m;
    }

    // ---- output partials: per k, 16 loads (8 Z + 8 Y) in flight ----
    float po[NC];
#pragma unroll
    for (int k = 0; k < NC; ++k) po[k] = 0.f;
    if (t < HW) {
#pragma unroll
        for (int k = 0; k < NC; ++k) {
            float z[SLABS], y[SLABS];
#pragma unroll
            for (int s = 0; s < SLABS; ++s)
                z[s] = g_part[((size_t)s * NOUT + 8 + k) * PART_N + g0 + t];
#pragma unroll
            for (int s = 0; s < SLABS; ++s)
                y[s] = g_part[((size_t)s * NOUT + 16 + k) * PART_N + g0 + t];
            float zs = ((z[0] + z[1]) + (z[2] + z[3])) +
                       ((z[4] + z[5]) + (z[6] + z[7]));
            float ys = ((y[0] + y[1]) + (y[2] + y[3])) +
                       ((y[4] + y[5]) + (y[6] + y[7]));
            po[k] = fmaf(m, ys, zs);
        }
    }
#pragma unroll
    for (int o = 16; o; o >>= 1) {
#pragma unroll
        for (int k = 0; k < NC; ++k)
            po[k] += __shfl_down_sync(0xffffffffu, po[k], o);
    }
    const int lane = t & 31, warp = t >> 5;
    if (lane == 0) {
#pragma unroll
        for (int k = 0; k < NC; ++k) wpart[warp][k] = po[k];
    }
    __syncthreads();
    if (t < NC) {
        float s = 0.f;
#pragma unroll
        for (int w = 0; w < 7; ++w) s += wpart[w][t];
        out_output[b * NC + t] = s * (1.0f / (float)HW) + b_cls[t];
    }
}

// ============================================================================
// kernel_launch: 2 launches, graph-capturable, deterministic.
// Output layout: v[128,8]@0, output[128,8]@1024, m[128,196]@2048,
//                m_c[128,8,196]@27136.
// ============================================================================
extern "C" void kernel_launch(void* const* d_in, const int* in_sizes, int n_in,
                              void* d_out, int out_size) {
    const float* x      = (const float*)d_in[0];
    const float* w_down = (const float*)d_in[1];
    const float* b_down = (const float*)d_in[2];
    const float* w_cls  = (const float*)d_in[3];
    const float* b_cls  = (const float*)d_in[4];

    float* out        = (float*)d_out;
    float* out_v      = out;
    float* out_output = out + 1024;
    float* out_m      = out + 2048;
    float* out_mc     = out + 27136;

    k1_main<<<dim3(PART_N / 256, SLABS), 256>>>(x, w_down, w_cls);
    k2_epi<<<B_DIM, 224>>>(b_down, b_cls, out_v, out_output, out_m, out_mc);
}

// round 8
// speedup vs baseline: 1.3301x; 1.3301x over previous
#include <cuda_runtime.h>

#define B_DIM 128
#define C_DIM 2048
#define HW 196
#define NC 8
#define NM 4
#define PART_N (B_DIM * HW)        // 25088
#define SLABS 16
#define CSLAB (C_DIM / SLABS)      // 128
#define PXB 512                    // pixels per k1 block (2 per thread)
#define NGRP 64                    // channel groups of 32 for pass 2

// ---- scratch (__device__ globals; no allocation allowed) ----
__device__ float g_part[SLABS * NC * PART_N];   // A slab-partials, 12.8 MB
__device__ float g_po[B_DIM * NGRP * NC];       // per-group output partials

// ---------------- packed f32x2 helpers ----------------
__device__ __forceinline__ unsigned long long fma2(
    unsigned long long a, unsigned long long b, unsigned long long c) {
    unsigned long long d;
    asm("fma.rn.f32x2 %0, %1, %2, %3;" : "=l"(d) : "l"(a), "l"(b), "l"(c));
    return d;
}
__device__ __forceinline__ unsigned long long dup2(float v) {
    unsigned long long d;
    asm("mov.b64 %0, {%1, %2};" : "=l"(d) : "f"(v), "f"(v));
    return d;
}
__device__ __forceinline__ void unpack2(unsigned long long v, float& lo, float& hi) {
    asm("mov.b64 {%0, %1}, %2;" : "=f"(lo), "=f"(hi) : "l"(v));
}

// ============================================================================
// K1: per-pixel A maps. grid (49, 16), 256 threads, 4 blocks/SM.
// Thread owns TWO adjacent pixels (g0, g0+1) -> float2 LDG; the two pixels
// share each channel's weight LDS.128s, halving LDS+LDG issue per FMA.
// 16-channel LDG batches (MLP 16) cover DRAM latency.
// ============================================================================
__global__ void __launch_bounds__(256, 4) k1_main(
    const float* __restrict__ x,
    const float* __restrict__ w_down) {
    __shared__ float wsh[CSLAB * NC];   // 4 KB

    const int slab = blockIdx.y;
    const int t = threadIdx.x;

    // inline weight fold: threads 0..127 own local channel t
    if (t < CSLAB) {
        const int cg = slab * CSLAB + t;
        float* w = &wsh[t * NC];
#pragma unroll
        for (int k = 0; k < NC; ++k) {
            float s0 = w_down[(k * NM + 0) * C_DIM + cg];
            float s1 = w_down[(k * NM + 1) * C_DIM + cg];
            float s2 = w_down[(k * NM + 2) * C_DIM + cg];
            float s3 = w_down[(k * NM + 3) * C_DIM + cg];
            w[k] = 0.25f * ((s0 + s1) + (s2 + s3));
        }
    }
    __syncthreads();

    const int g0 = blockIdx.x * PXB + 2 * t;   // pixels g0, g0+1 (same batch: HW even)
    const int b = g0 / HW;
    const int p = g0 - b * HW;

    unsigned long long acc0[4], acc1[4];
#pragma unroll
    for (int j = 0; j < 4; ++j) { acc0[j] = dup2(0.f); acc1[j] = dup2(0.f); }

    const float* xp = x + (size_t)b * C_DIM * HW + (size_t)(slab * CSLAB) * HW + p;

#pragma unroll 1
    for (int c0 = 0; c0 < CSLAB; c0 += 16) {
        // front-batch 16 independent float2 loads (MLP = 16)
        float2 xv[16];
#pragma unroll
        for (int u = 0; u < 16; ++u)
            xv[u] = *(const float2*)&xp[(c0 + u) * HW];
#pragma unroll
        for (int u = 0; u < 16; ++u) {
            unsigned long long xx0 = dup2(xv[u].x);
            unsigned long long xx1 = dup2(xv[u].y);
            const ulonglong2* w = (const ulonglong2*)&wsh[(c0 + u) * NC];
            ulonglong2 w0 = w[0];
            ulonglong2 w1 = w[1];
            acc0[0] = fma2(xx0, w0.x, acc0[0]);
            acc1[0] = fma2(xx1, w0.x, acc1[0]);
            acc0[1] = fma2(xx0, w0.y, acc0[1]);
            acc1[1] = fma2(xx1, w0.y, acc1[1]);
            acc0[2] = fma2(xx0, w1.x, acc0[2]);
            acc1[2] = fma2(xx1, w1.x, acc1[2]);
            acc0[3] = fma2(xx0, w1.y, acc0[3]);
            acc1[3] = fma2(xx1, w1.y, acc1[3]);
        }
    }

    // write 8 outputs x 2 pixels as float2 stores (g0 even -> aligned)
    float* base = &g_part[(size_t)slab * NC * PART_N + g0];
#pragma unroll
    for (int j = 0; j < 4; ++j) {
        float lo0, hi0, lo1, hi1;
        unpack2(acc0[j], lo0, hi0);   // pixel g0:  k=2j, k=2j+1
        unpack2(acc1[j], lo1, hi1);   // pixel g0+1
        *(float2*)&base[(2 * j) * PART_N]     = make_float2(lo0, lo1);
        *(float2*)&base[(2 * j + 1) * PART_N] = make_float2(hi0, hi1);
    }
}

// ============================================================================
// K2: per-batch epilogue for pass 1. 128 blocks x 224 threads.
//   m_c[k,p] = sum_s A_part + beff[k]; v[k] = mean_p m_c;
//   m[p] = (1/8) sum_k v[k]*m_c[k,p]
// 16 partial loads front-batched per class.
// ============================================================================
__global__ void __launch_bounds__(224) k2_epi(
    const float* __restrict__ b_down,
    float* __restrict__ out_v,
    float* __restrict__ out_m,
    float* __restrict__ out_mc) {
    __shared__ float red[NC * 200];
    __shared__ float vsh[NC];
    __shared__ float besh[NC];

    const int b = blockIdx.x;
    const int t = threadIdx.x;
    const int g0 = b * HW;

    if (t < NC)
        besh[t] = 0.25f * (b_down[4 * t] + b_down[4 * t + 1] +
                           b_down[4 * t + 2] + b_down[4 * t + 3]);
    __syncthreads();

    if (t < HW) {
#pragma unroll
        for (int k = 0; k < NC; ++k) {
            float a[SLABS];
#pragma unroll
            for (int s = 0; s < SLABS; ++s)
                a[s] = g_part[((size_t)s * NC + k) * PART_N + g0 + t];
            float s4[4];
#pragma unroll
            for (int q = 0; q < 4; ++q)
                s4[q] = (a[4 * q] + a[4 * q + 1]) + (a[4 * q + 2] + a[4 * q + 3]);
            float mc = ((s4[0] + s4[1]) + (s4[2] + s4[3])) + besh[k];
            red[k * 200 + t] = mc;
            out_mc[((size_t)b * NC + k) * HW + t] = mc;
        }
    }
    __syncthreads();

    if (t < NC) {
        float s = 0.f;
        for (int p = 0; p < HW; ++p) s += red[t * 200 + p];
        float vv = s * (1.0f / (float)HW);
        vsh[t] = vv;
        out_v[b * NC + t] = vv;
    }
    __syncthreads();

    if (t < HW) {
        float m = 0.f;
#pragma unroll
        for (int k = 0; k < NC; ++k) m = fmaf(vsh[k], red[k * 200 + t], m);
        out_m[b * HW + t] = m * (1.0f / (float)NC);
    }
}

// ============================================================================
// K3: second streaming x pass, fused with the output dot-product.
// grid (NGRP=64, B=128), 256 threads (8 warps). Warp w owns 4 channels;
// all 8 row-LDG.128s issued up front (MLP 8).
// ============================================================================
__global__ void __launch_bounds__(256) k3_gap(
    const float* __restrict__ x,
    const float* __restrict__ m_in,
    const float* __restrict__ w_cls) {
    __shared__ float4 msh4[49];
    __shared__ float gxs[32];
    __shared__ float gus[32];

    const int b = blockIdx.y;
    const int grp = blockIdx.x;
    const int t = threadIdx.x;
    const int w = t >> 5, l = t & 31;

    if (t < 49) msh4[t] = ((const float4*)(m_in + b * HW))[t];
    __syncthreads();

    const int cbase = grp * 32 + w * 4;
    const float* rowb = x + ((size_t)b * C_DIM + cbase) * HW;
    const bool tail = (l < 17);

    float4 xa[4], xb[4];
#pragma unroll
    for (int i = 0; i < 4; ++i)
        xa[i] = ((const float4*)(rowb + i * HW))[l];
#pragma unroll
    for (int i = 0; i < 4; ++i)
        xb[i] = tail ? ((const float4*)(rowb + i * HW))[l + 32]
                     : make_float4(0.f, 0.f, 0.f, 0.f);

    float4 ma = msh4[l];
    float4 mb = tail ? msh4[l + 32] : make_float4(0.f, 0.f, 0.f, 0.f);

#pragma unroll
    for (int i = 0; i < 4; ++i) {
        float s1 = ((xa[i].x + xa[i].y) + (xa[i].z + xa[i].w)) +
                   ((xb[i].x + xb[i].y) + (xb[i].z + xb[i].w));
        float s2 = fmaf(xa[i].x, ma.x, fmaf(xa[i].y, ma.y,
                   fmaf(xa[i].z, ma.z, xa[i].w * ma.w)));
        s2 = fmaf(xb[i].x, mb.x, fmaf(xb[i].y, mb.y,
             fmaf(xb[i].z, mb.z, fmaf(xb[i].w, mb.w, s2))));
#pragma unroll
        for (int o = 16; o; o >>= 1) {
            s1 += __shfl_xor_sync(0xffffffffu, s1, o);
            s2 += __shfl_xor_sync(0xffffffffu, s2, o);
        }
        if (l == 0) {
            gxs[w * 4 + i] = s1 * (1.0f / (float)HW);
            gus[w * 4 + i] = s2 * (1.0f / (float)HW);
        }
    }
    __syncthreads();

    // output partial: warp w = class k; lane l = local channel
    {
        const int c = grp * 32 + l;
        float gx = gxs[l];
        float gu = gus[l];
        float val = fmaf(w_cls[w * 2 * C_DIM + c], gx,
                         w_cls[w * 2 * C_DIM + C_DIM + c] * gu);
#pragma unroll
        for (int o = 16; o; o >>= 1)
            val += __shfl_down_sync(0xffffffffu, val, o);
        if (l == 0)
            g_po[((size_t)b * NGRP + grp) * NC + w] = val;
    }
}

// ============================================================================
// K4: output[b,k] = sum_grp po[b,grp,k] + b_cls[k]. grid 128, 256 threads:
// warp w = class k, lanes cover the 64 groups (2 each).
// ============================================================================
__global__ void __launch_bounds__(256) k4_out(
    const float* __restrict__ b_cls,
    float* __restrict__ out_output) {
    const int b = blockIdx.x;
    const int t = threadIdx.x;
    const int w = t >> 5, l = t & 31;

    float v = g_po[((size_t)b * NGRP + l) * NC + w] +
              g_po[((size_t)b * NGRP + l + 32) * NC + w];
#pragma unroll
    for (int o = 16; o; o >>= 1)
        v += __shfl_down_sync(0xffffffffu, v, o);
    if (l == 0)
        out_output[b * NC + w] = v + b_cls[w];
}

// ============================================================================
// Output layout: v[128,8]@0, output[128,8]@1024, m[128,196]@2048,
//                m_c[128,8,196]@27136.
// ============================================================================
extern "C" void kernel_launch(void* const* d_in, const int* in_sizes, int n_in,
                              void* d_out, int out_size) {
    const float* x      = (const float*)d_in[0];
    const float* w_down = (const float*)d_in[1];
    const float* b_down = (const float*)d_in[2];
    const float* w_cls  = (const float*)d_in[3];
    const float* b_cls  = (const float*)d_in[4];

    float* out        = (float*)d_out;
    float* out_v      = out;
    float* out_output = out + 1024;
    float* out_m      = out + 2048;
    float* out_mc     = out + 27136;

    k1_main<<<dim3(PART_N / PXB, SLABS), 256>>>(x, w_down);
    k2_epi<<<B_DIM, 224>>>(b_down, out_v, out_m, out_mc);
    k3_gap<<<dim3(NGRP, B_DIM), 256>>>(x, out_m, w_cls);
    k4_out<<<B_DIM, 256>>>(b_cls, out_output);
}

// round 10
// speedup vs baseline: 1.3861x; 1.0421x over previous
#include <cuda_runtime.h>

#define B_DIM 128
#define C_DIM 2048
#define HW 196
#define NC 8
#define NM 4
#define NOUT 24                    // 8 A + 8 Z + 8 Y per pixel
#define PART_N (B_DIM * HW)        // 25088
#define SLABS 8
#define CSLAB (C_DIM / SLABS)      // 256
#define PXT 4                      // pixels per thread
#define K1_THREADS 128
#define PXB (K1_THREADS * PXT)     // 512 pixels per block

// ---- scratch (__device__ globals; no allocation allowed) ----
// slab-partial per-pixel outputs: [slab][out24][g]  (19.3 MB)
__device__ float g_part[SLABS * NOUT * PART_N];

// ---------------- packed f32x2 helpers ----------------
__device__ __forceinline__ unsigned long long fma2(
    unsigned long long a, unsigned long long b, unsigned long long c) {
    unsigned long long d;
    asm("fma.rn.f32x2 %0, %1, %2, %3;" : "=l"(d) : "l"(a), "l"(b), "l"(c));
    return d;
}
__device__ __forceinline__ unsigned long long dup2(float v) {
    unsigned long long d;
    asm("mov.b64 %0, {%1, %2};" : "=l"(d) : "f"(v), "f"(v));
    return d;
}
__device__ __forceinline__ void unpack2(unsigned long long v, float& lo, float& hi) {
    asm("mov.b64 {%0, %1}, %2;" : "=f"(lo), "=f"(hi) : "l"(v));
}

// per-channel update: 4 pixels x 24 outputs (12 packed k-pairs per pixel).
// acc[j*PXT + px] = packed pair (out 2j, out 2j+1) of pixel px.
__device__ __forceinline__ void chan_update(
    const float4 xv, const float* wrow, unsigned long long* acc) {
    unsigned long long xx[PXT];
    xx[0] = dup2(xv.x); xx[1] = dup2(xv.y);
    xx[2] = dup2(xv.z); xx[3] = dup2(xv.w);
    const ulonglong2* w = (const ulonglong2*)wrow;   // 96 B row, 16B-aligned
#pragma unroll
    for (int h = 0; h < 6; ++h) {
        ulonglong2 wv = w[h];                        // pairs (4h,4h+1),(4h+2,4h+3)
#pragma unroll
        for (int px = 0; px < PXT; ++px) {
            acc[(2 * h) * PXT + px]     = fma2(xx[px], wv.x, acc[(2 * h) * PXT + px]);
            acc[(2 * h + 1) * PXT + px] = fma2(xx[px], wv.y, acc[(2 * h + 1) * PXT + px]);
        }
    }
}

// ============================================================================
// K1: SINGLE streaming pass over x. grid (49, 8), 128 threads, 3 blocks/SM.
// Thread owns 4 adjacent pixels (g0..g0+3, same batch since 4|196) -> float4
// LDG; per channel the 4 pixels share the 6 weight LDS.128s.
//   A[k]=w_eff·x, Z[k]=w_lo·x, Y[k]=w_hi·x.
// ============================================================================
__global__ void __launch_bounds__(K1_THREADS, 3) k1_main(
    const float* __restrict__ x,
    const float* __restrict__ w_down,
    const float* __restrict__ w_cls) {
    __shared__ float wsh[CSLAB * NOUT];   // 24 KB

    const int slab = blockIdx.y;
    const int t = threadIdx.x;

    // ---- inline weight prep: thread t owns local channels t, t+128 ----
#pragma unroll
    for (int cl = t; cl < CSLAB; cl += K1_THREADS) {
        const int cg = slab * CSLAB + cl;
        float* w = &wsh[cl * NOUT];
#pragma unroll
        for (int k = 0; k < NC; ++k) {
            float s0 = w_down[(k * NM + 0) * C_DIM + cg];
            float s1 = w_down[(k * NM + 1) * C_DIM + cg];
            float s2 = w_down[(k * NM + 2) * C_DIM + cg];
            float s3 = w_down[(k * NM + 3) * C_DIM + cg];
            w[k]      = 0.25f * ((s0 + s1) + (s2 + s3));
            w[8 + k]  = w_cls[k * 2 * C_DIM + cg];
            w[16 + k] = w_cls[k * 2 * C_DIM + C_DIM + cg];
        }
    }
    __syncthreads();

    const int g0 = blockIdx.x * PXB + PXT * t;   // 4 pixels, same batch (4|196)
    const int b = g0 / HW;
    const int p = g0 - b * HW;

    unsigned long long acc[12 * PXT];
#pragma unroll
    for (int j = 0; j < 12 * PXT; ++j) acc[j] = dup2(0.f);

    const float* xp = x + ((size_t)b * C_DIM + slab * CSLAB) * HW + p;

#pragma unroll 1
    for (int c0 = 0; c0 < CSLAB; c0 += 4) {
        // front-batch 4 independent float4 loads
        float4 xv[4];
#pragma unroll
        for (int u = 0; u < 4; ++u)
            xv[u] = *(const float4*)&xp[(c0 + u) * HW];
#pragma unroll
        for (int u = 0; u < 4; ++u)
            chan_update(xv[u], &wsh[(c0 + u) * NOUT], acc);
    }

    // write 24 output rows x 4 pixels as float4 (g0 multiple of 4 -> aligned).
    // acc[j*PXT+px] = pair (out 2j, out 2j+1) of pixel px.
    float* base = &g_part[(size_t)slab * NOUT * PART_N + g0];
#pragma unroll
    for (int j = 0; j < 12; ++j) {
        float lo[PXT], hi[PXT];
#pragma unroll
        for (int px = 0; px < PXT; ++px)
            unpack2(acc[j * PXT + px], lo[px], hi[px]);
        *(float4*)&base[(2 * j) * PART_N] =
            make_float4(lo[0], lo[1], lo[2], lo[3]);
        *(float4*)&base[(2 * j + 1) * PART_N] =
            make_float4(hi[0], hi[1], hi[2], hi[3]);
    }
}

// ============================================================================
// K2a: per (k, b) block: m_c[b,k,p] = sum_s A_part + beff[k] -> out_mc;
//      v[b,k] = mean_p m_c -> out_v.   grid (8, 128) x 224 threads.
// ============================================================================
__global__ void __launch_bounds__(224) k2a(
    const float* __restrict__ b_down,
    float* __restrict__ out_v,
    float* __restrict__ out_mc) {
    __shared__ float wpart[7];
    const int k = blockIdx.x;
    const int b = blockIdx.y;
    const int t = threadIdx.x;
    const int g0 = b * HW;

    float mc = 0.f;
    if (t < HW) {
        float a[SLABS];
#pragma unroll
        for (int s = 0; s < SLABS; ++s)
            a[s] = g_part[((size_t)s * NOUT + k) * PART_N + g0 + t];
        float sum = ((a[0] + a[1]) + (a[2] + a[3])) +
                    ((a[4] + a[5]) + (a[6] + a[7]));
        float beff = 0.25f * ((b_down[4 * k] + b_down[4 * k + 1]) +
                              (b_down[4 * k + 2] + b_down[4 * k + 3]));
        mc = sum + beff;
        out_mc[((size_t)b * NC + k) * HW + t] = mc;
    }
    // block reduce for v
    float s = mc;
#pragma unroll
    for (int o = 16; o; o >>= 1) s += __shfl_down_sync(0xffffffffu, s, o);
    const int lane = t & 31, warp = t >> 5;
    if (lane == 0) wpart[warp] = s;
    __syncthreads();
    if (t == 0) {
        float tot = 0.f;
#pragma unroll
        for (int w = 0; w < 7; ++w) tot += wpart[w];
        out_v[b * NC + k] = tot * (1.0f / (float)HW);
    }
}

// ============================================================================
// K2b: m[b,p] = (1/NC) sum_k v[b,k]*m_c[b,k,p].  grid 128 x 224.
// ============================================================================
__global__ void __launch_bounds__(224) k2b(
    const float* __restrict__ v_in,
    const float* __restrict__ mc_in,
    float* __restrict__ out_m) {
    __shared__ float vsh[NC];
    const int b = blockIdx.x;
    const int t = threadIdx.x;
    if (t < NC) vsh[t] = v_in[b * NC + t];
    __syncthreads();
    if (t < HW) {
        float a[NC];
#pragma unroll
        for (int k = 0; k < NC; ++k)
            a[k] = mc_in[((size_t)b * NC + k) * HW + t];
        float m = 0.f;
#pragma unroll
        for (int k = 0; k < NC; ++k) m = fmaf(vsh[k], a[k], m);
        out_m[b * HW + t] = m * (1.0f / (float)NC);
    }
}

// ============================================================================
// K2c: output[b,k] = (1/HW) sum_p (Z[k,p] + m[p]*Y[k,p]) + b_cls[k].
// grid (8, 128) x 224 threads; 17 loads front-batched per thread.
// ============================================================================
__global__ void __launch_bounds__(224) k2c(
    const float* __restrict__ m_in,
    const float* __restrict__ b_cls,
    float* __restrict__ out_output) {
    __shared__ float wpart[7];
    const int k = blockIdx.x;
    const int b = blockIdx.y;
    const int t = threadIdx.x;
    const int g0 = b * HW;

    float po = 0.f;
    if (t < HW) {
        float z[SLABS], y[SLABS];
#pragma unroll
        for (int s = 0; s < SLABS; ++s)
            z[s] = g_part[((size_t)s * NOUT + 8 + k) * PART_N + g0 + t];
#pragma unroll
        for (int s = 0; s < SLABS; ++s)
            y[s] = g_part[((size_t)s * NOUT + 16 + k) * PART_N + g0 + t];
        float m = m_in[b * HW + t];
        float zs = ((z[0] + z[1]) + (z[2] + z[3])) +
                   ((z[4] + z[5]) + (z[6] + z[7]));
        float ys = ((y[0] + y[1]) + (y[2] + y[3])) +
                   ((y[4] + y[5]) + (y[6] + y[7]));
        po = fmaf(m, ys, zs);
    }
    float s = po;
#pragma unroll
    for (int o = 16; o; o >>= 1) s += __shfl_down_sync(0xffffffffu, s, o);
    const int lane = t & 31, warp = t >> 5;
    if (lane == 0) wpart[warp] = s;
    __syncthreads();
    if (t == 0) {
        float tot = 0.f;
#pragma unroll
        for (int w = 0; w < 7; ++w) tot += wpart[w];
        out_output[b * NC + k] = tot * (1.0f / (float)HW) + b_cls[k];
    }
}

// ============================================================================
// kernel_launch: 4 launches, graph-capturable, deterministic.
// Output layout: v[128,8]@0, output[128,8]@1024, m[128,196]@2048,
//                m_c[128,8,196]@27136.
// ============================================================================
extern "C" void kernel_launch(void* const* d_in, const int* in_sizes, int n_in,
                              void* d_out, int out_size) {
    const float* x      = (const float*)d_in[0];
    const float* w_down = (const float*)d_in[1];
    const float* b_down = (const float*)d_in[2];
    const float* w_cls  = (const float*)d_in[3];
    const float* b_cls  = (const float*)d_in[4];

    float* out        = (float*)d_out;
    float* out_v      = out;
    float* out_output = out + 1024;
    float* out_m      = out + 2048;
    float* out_mc     = out + 27136;

    k1_main<<<dim3(PART_N / PXB, SLABS), K1_THREADS>>>(x, w_down, w_cls);
    k2a<<<dim3(NC, B_DIM), 224>>>(b_down, out_v, out_mc);
    k2b<<<B_DIM, 224>>>(out_v, out_mc, out_m);
    k2c<<<dim3(NC, B_DIM), 224>>>(out_m, b_cls, out_output);
}